// round 5
// baseline (speedup 1.0000x reference)
#include <cuda_runtime.h>
#include <cstdint>

#define BB   64
#define SS   1024
#define II   256
#define HH   256
#define G3   768
#define CPAD 68   // padded chunk stride: 32 data + 36 pad; 68%32==4 (distinct banks), 272B (16B aligned)

typedef unsigned long long u64;

// Scratch for input-side gate projections: [B*S, 768] fp32
__device__ float g_xg[(size_t)BB * SS * G3];

__device__ __forceinline__ u64 ffma2(u64 a, u64 b, u64 c) {
    u64 d; asm("fma.rn.f32x2 %0, %1, %2, %3;" : "=l"(d) : "l"(a), "l"(b), "l"(c)); return d;
}
__device__ __forceinline__ float rcpa(float x) {
    float y; asm("rcp.approx.f32 %0, %1;" : "=f"(y) : "f"(x)); return y;
}
__device__ __forceinline__ float2 unpack2(u64 v) {
    float2 f; asm("mov.b64 {%0, %1}, %2;" : "=f"(f.x), "=f"(f.y) : "l"(v)); return f;
}
__device__ __forceinline__ u64 packdup(float x) {
    u64 v; asm("mov.b64 %0, {%1, %2};" : "=l"(v) : "f"(x), "f"(x)); return v;
}
__device__ __forceinline__ uint32_t smem_u32(const void* p) {
    return (uint32_t)__cvta_generic_to_shared(p);
}

// ---------------------------------------------------------------------------
// GEMM with f32x2 packed FMA (unchanged, passing).
// g_xg[r,g] = sum_i X[r*lda+i]*W[g*256+i] + bias[g]
// ---------------------------------------------------------------------------
__global__ void __launch_bounds__(256)
gemm_xg_kernel(const float* __restrict__ X, long lda,
               const float* __restrict__ W, const float* __restrict__ bias)
{
    __shared__ alignas(16) float As[16][132];
    __shared__ alignas(16) float Bs[16][68];

    const int t   = threadIdx.x;
    const int tx  = t & 15;
    const int ty  = t >> 4;
    const int r0  = blockIdx.y * 128;
    const int g0  = blockIdx.x * 64;

    const int arow = t >> 2;
    const int ak   = (t & 3) * 4;

    u64 acc2[4][4];
#pragma unroll
    for (int i = 0; i < 4; i++)
#pragma unroll
        for (int j = 0; j < 4; j++) acc2[i][j] = 0ull;

    for (int kt = 0; kt < 16; kt++) {
        const int k0 = kt * 16;
        float4 a0 = *reinterpret_cast<const float4*>(X + (size_t)(r0 + arow) * lda + k0 + ak);
        float4 a1 = *reinterpret_cast<const float4*>(X + (size_t)(r0 + arow + 64) * lda + k0 + ak);
        As[ak + 0][arow] = a0.x; As[ak + 1][arow] = a0.y;
        As[ak + 2][arow] = a0.z; As[ak + 3][arow] = a0.w;
        As[ak + 0][arow + 64] = a1.x; As[ak + 1][arow + 64] = a1.y;
        As[ak + 2][arow + 64] = a1.z; As[ak + 3][arow + 64] = a1.w;
        float4 bv = *reinterpret_cast<const float4*>(W + (size_t)(g0 + arow) * 256 + k0 + ak);
        Bs[ak + 0][arow] = bv.x; Bs[ak + 1][arow] = bv.y;
        Bs[ak + 2][arow] = bv.z; Bs[ak + 3][arow] = bv.w;
        __syncthreads();

#pragma unroll
        for (int kk = 0; kk < 16; kk++) {
            const u64* ap = reinterpret_cast<const u64*>(&As[kk][ty * 8]);
            u64 pa0 = ap[0], pa1 = ap[1], pa2 = ap[2], pa3 = ap[3];
            float4 bv4 = *reinterpret_cast<const float4*>(&Bs[kk][tx * 4]);
            u64 pb0 = packdup(bv4.x), pb1 = packdup(bv4.y);
            u64 pb2 = packdup(bv4.z), pb3 = packdup(bv4.w);
            acc2[0][0] = ffma2(pa0, pb0, acc2[0][0]);
            acc2[0][1] = ffma2(pa0, pb1, acc2[0][1]);
            acc2[0][2] = ffma2(pa0, pb2, acc2[0][2]);
            acc2[0][3] = ffma2(pa0, pb3, acc2[0][3]);
            acc2[1][0] = ffma2(pa1, pb0, acc2[1][0]);
            acc2[1][1] = ffma2(pa1, pb1, acc2[1][1]);
            acc2[1][2] = ffma2(pa1, pb2, acc2[1][2]);
            acc2[1][3] = ffma2(pa1, pb3, acc2[1][3]);
            acc2[2][0] = ffma2(pa2, pb0, acc2[2][0]);
            acc2[2][1] = ffma2(pa2, pb1, acc2[2][1]);
            acc2[2][2] = ffma2(pa2, pb2, acc2[2][2]);
            acc2[2][3] = ffma2(pa2, pb3, acc2[2][3]);
            acc2[3][0] = ffma2(pa3, pb0, acc2[3][0]);
            acc2[3][1] = ffma2(pa3, pb1, acc2[3][1]);
            acc2[3][2] = ffma2(pa3, pb2, acc2[3][2]);
            acc2[3][3] = ffma2(pa3, pb3, acc2[3][3]);
        }
        __syncthreads();
    }

    float4 b4 = *reinterpret_cast<const float4*>(bias + g0 + tx * 4);
#pragma unroll
    for (int i = 0; i < 4; i++) {
        float2 c0 = unpack2(acc2[i][0]), c1 = unpack2(acc2[i][1]);
        float2 c2 = unpack2(acc2[i][2]), c3 = unpack2(acc2[i][3]);
        size_t row0 = (size_t)(r0 + ty * 8 + 2 * i);
        float4 v0, v1;
        v0.x = c0.x + b4.x; v0.y = c1.x + b4.y; v0.z = c2.x + b4.z; v0.w = c3.x + b4.w;
        v1.x = c0.y + b4.x; v1.y = c1.y + b4.y; v1.z = c2.y + b4.z; v1.w = c3.y + b4.w;
        *reinterpret_cast<float4*>(&g_xg[row0 * G3 + g0 + tx * 4]) = v0;
        *reinterpret_cast<float4*>(&g_xg[(row0 + 1) * G3 + g0 + tx * 4]) = v1;
    }
}

// ---------------------------------------------------------------------------
// Persistent GRU scan, barrier-free inner loop:
//  - leaders st.async their hnew directly to all 4 ranks (no stage, no
//    __syncthreads) with complete_tx on double-buffered mbarriers
//  - LDS.128 hidden-state reads (CPAD=68: conflict-free, 16B aligned)
//  - mapa bases hoisted out of the loop
// ---------------------------------------------------------------------------
__global__ void __cluster_dims__(4, 1, 1) __launch_bounds__(512, 1)
gru_scan_kernel(const float* __restrict__ Whh,   // [768,256]
                const float* __restrict__ bhh,   // [768]
                float* __restrict__ out, int ostride,
                float* __restrict__ out2, int ostride2)  // may be null
{
    // [parity][sb][chunk][CPAD]; h element j at [.][sb][j>>5][j&31]
    __shared__ alignas(16) float hbuf[2][2][8][CPAD];
    __shared__ alignas(8)  u64   mbars[2];

    const int c    = blockIdx.x;               // cluster rank
    const int tid  = threadIdx.x;
    const int warp = tid >> 5;
    const int lane = tid & 31;
    const int ul   = warp * 4 + (lane >> 3);   // local unit 0..63
    const int jg   = c * 64 + ul;              // global hidden unit
    const int kc   = lane & 7;                 // k-chunk 0..7
    const bool leader = kc == 0;
    const int b0   = blockIdx.y * 2;

    // recurrent weights -> registers as f32x2 pairs, k base = kc*32
    u64 wr2[16], wz2[16], wn2[16];
    {
        const int k0 = kc * 32;
        const u64* pr = reinterpret_cast<const u64*>(Whh + (size_t)jg * HH + k0);
        const u64* pz = reinterpret_cast<const u64*>(Whh + (size_t)(256 + jg) * HH + k0);
        const u64* pq = reinterpret_cast<const u64*>(Whh + (size_t)(512 + jg) * HH + k0);
#pragma unroll
        for (int i = 0; i < 16; i++) { wr2[i] = pr[i]; wz2[i] = pz[i]; wn2[i] = pq[i]; }
    }
    float bhr = 0.f, bhz = 0.f, bhn = 0.f;
    if (leader) { bhr = bhh[jg]; bhz = bhh[256 + jg]; bhn = bhh[512 + jg]; }

    // zero parity-0 buffer
    for (int i = tid; i < 2 * 8 * CPAD; i += 512) ((float*)hbuf[0])[i] = 0.f;
    const uint32_t mb = smem_u32(mbars);
    const uint32_t hb = smem_u32(hbuf);
    if (tid == 0) {
        asm volatile("mbarrier.init.shared.b64 [%0], 1;" :: "r"(mb)     : "memory");
        asm volatile("mbarrier.init.shared.b64 [%0], 1;" :: "r"(mb + 8) : "memory");
    }
    __syncthreads();
    asm volatile("barrier.cluster.arrive.aligned;" ::: "memory");
    asm volatile("barrier.cluster.wait.aligned;"   ::: "memory");

    // hoisted per-rank remote base addresses
    uint32_t hb_r[4], mb_r[4];
#pragma unroll
    for (int r = 0; r < 4; r++) {
        asm volatile("mapa.shared::cluster.u32 %0, %1, %2;" : "=r"(hb_r[r]) : "r"(hb), "r"(r));
        asm volatile("mapa.shared::cluster.u32 %0, %1, %2;" : "=r"(mb_r[r]) : "r"(mb), "r"(r));
    }

    // prefetch xg for t=0 (leaders)
    float xpr[2], xpz[2], xpn[2];
    if (leader) {
#pragma unroll
        for (int sb = 0; sb < 2; sb++) {
            size_t base = ((size_t)(b0 + sb) * SS) * G3;
            xpr[sb] = __ldg(&g_xg[base + jg]);
            xpz[sb] = __ldg(&g_xg[base + 256 + jg]);
            xpn[sb] = __ldg(&g_xg[base + 512 + jg]);
        }
    }

    const int hchunk = jg >> 5;                 // chunk of own unit
    const int hoff   = jg & 31;
    const uint32_t parity_stride = (uint32_t)(2 * 8 * CPAD * 4);

    int ph0 = 0, ph1 = 0;

    for (int t = 0; t < SS; t++) {
        const int p = t & 1, pq = p ^ 1;
        if (tid == 0) {
            // arm receive barrier for hbuf[pq]: 4 CTAs x 64 leaders x 2 sb x 4B
            asm volatile("mbarrier.arrive.expect_tx.shared.b64 _, [%0], %1;"
                         :: "r"(mb + pq * 8), "r"(2048u) : "memory");
        }
        float xr[2], xz[2], xn[2];
        if (leader) {
#pragma unroll
            for (int sb = 0; sb < 2; sb++) { xr[sb]=xpr[sb]; xz[sb]=xpz[sb]; xn[sb]=xpn[sb]; }
            const int tn = (t + 1 < SS) ? t + 1 : t;
#pragma unroll
            for (int sb = 0; sb < 2; sb++) {
                size_t base = ((size_t)(b0 + sb) * SS + tn) * G3;
                xpr[sb] = __ldg(&g_xg[base + jg]);
                xpz[sb] = __ldg(&g_xg[base + 256 + jg]);
                xpn[sb] = __ldg(&g_xg[base + 512 + jg]);
            }
        }

#pragma unroll
        for (int sb = 0; sb < 2; sb++) {
            const ulonglong2* hp =
                reinterpret_cast<const ulonglong2*>(&hbuf[p][sb][kc][0]);
            u64 aR = 0ull, aZ = 0ull, aN = 0ull;
#pragma unroll
            for (int i = 0; i < 8; i++) {
                ulonglong2 hv = hp[i];          // LDS.128, 1 wavefront
                aR = ffma2(wr2[2*i],   hv.x, aR);
                aZ = ffma2(wz2[2*i],   hv.x, aZ);
                aN = ffma2(wn2[2*i],   hv.x, aN);
                aR = ffma2(wr2[2*i+1], hv.y, aR);
                aZ = ffma2(wz2[2*i+1], hv.y, aZ);
                aN = ffma2(wn2[2*i+1], hv.y, aN);
            }
            float2 fR = unpack2(aR), fZ = unpack2(aZ), fN = unpack2(aN);
            float sR = fR.x + fR.y, sZ = fZ.x + fZ.y, sN = fN.x + fN.y;
#pragma unroll
            for (int d = 4; d; d >>= 1) {
                sR += __shfl_down_sync(0xffffffffu, sR, d);
                sZ += __shfl_down_sync(0xffffffffu, sZ, d);
                sN += __shfl_down_sync(0xffffffffu, sN, d);
            }
            if (leader) {
                float er = __expf(-(xr[sb] + sR + bhr));
                float r  = rcpa(1.f + er);
                float ez = __expf(-(xz[sb] + sZ + bhz));
                float z  = rcpa(1.f + ez);
                float na = xn[sb] + r * (sN + bhn);
                float en = __expf(-2.f * na);
                float n  = (1.f - en) * rcpa(1.f + en);
                float hold = hbuf[p][sb][hchunk][hoff];
                float hnew = n + z * (hold - n);

                size_t row = (size_t)(b0 + sb) * SS + t;
                out[row * ostride + jg] = hnew;
                if (out2) out2[row * ostride2 + jg] = hnew;

                // direct broadcast: 4B to each rank's hbuf[pq], tx on its mbar[pq]
                uint32_t doff = (uint32_t)pq * parity_stride
                              + (uint32_t)(((sb * 8 + hchunk) * CPAD + hoff) * 4);
                uint32_t moff = (uint32_t)(pq * 8);
#pragma unroll
                for (int r4 = 0; r4 < 4; r4++) {
                    asm volatile(
                        "st.async.shared::cluster.mbarrier::complete_tx::bytes.b32 [%0], %1, [%2];"
                        :: "r"(hb_r[r4] + doff), "f"(hnew), "r"(mb_r[r4] + moff) : "memory");
                }
            }
        }

        // wait for step t+1's h to fully land in our hbuf[pq]
        {
            uint32_t maddr = mb + pq * 8;
            uint32_t parity = pq ? ph1 : ph0;
            uint32_t done;
            asm volatile(
                "{\n\t.reg .pred p;\n\t"
                "mbarrier.try_wait.parity.acquire.cta.shared::cta.b64 p, [%1], %2;\n\t"
                "selp.b32 %0, 1, 0, p;\n\t}"
                : "=r"(done) : "r"(maddr), "r"(parity) : "memory");
            if (!done) {
                asm volatile(
                    "{\n\t.reg .pred P1;\n\t"
                    "WL_%=:\n\t"
                    "mbarrier.try_wait.parity.acquire.cta.shared::cta.b64 P1, [%0], %1, 0x989680;\n\t"
                    "@P1 bra.uni WD_%=;\n\t"
                    "bra.uni WL_%=;\n\t"
                    "WD_%=:\n\t}"
                    :: "r"(maddr), "r"(parity) : "memory");
            }
            if (pq) ph1 ^= 1; else ph0 ^= 1;
        }
    }
}

// ---------------------------------------------------------------------------
extern "C" void kernel_launch(void* const* d_in, const int* in_sizes, int n_in,
                              void* d_out, int out_size)
{
    (void)in_sizes; (void)n_in; (void)out_size;
    const float* inputs = (const float*)d_in[0];
    const float* W_ih0  = (const float*)d_in[1];
    const float* W_hh0  = (const float*)d_in[2];
    const float* b_ih0  = (const float*)d_in[3];
    const float* b_hh0  = (const float*)d_in[4];
    const float* W_ih1  = (const float*)d_in[5];
    const float* W_hh1  = (const float*)d_in[6];
    const float* b_ih1  = (const float*)d_in[7];
    const float* b_hh1  = (const float*)d_in[8];

    float* out    = (float*)d_out;
    float* h2     = out;                               // [B,S,H]
    float* concat = out + (size_t)BB * SS * HH;        // [B,S,2H]

    dim3 gemm_grid(G3 / 64, (BB * SS) / 128);
    dim3 scan_grid(4, BB / 2);

    // Layer 0: xg0 = inputs @ W_ih0^T + b_ih0; scan -> h1 in concat[:,:,0:256]
    gemm_xg_kernel<<<gemm_grid, 256>>>(inputs, (long)II, W_ih0, b_ih0);
    gru_scan_kernel<<<scan_grid, 512>>>(W_hh0, b_hh0, concat, 2 * HH, nullptr, 0);

    // Layer 1: xg1 = h1 @ W_ih1^T + b_ih1 (h1 read from concat, lda=512)
    gemm_xg_kernel<<<gemm_grid, 256>>>(concat, (long)(2 * HH), W_ih1, b_ih1);
    // scan -> h2 into concat[:,:,256:512] and into the h2 output (fused)
    gru_scan_kernel<<<scan_grid, 512>>>(W_hh1, b_hh1, concat + HH, 2 * HH, h2, HH);
}

// round 6
// speedup vs baseline: 1.6559x; 1.6559x over previous
#include <cuda_runtime.h>
#include <cstdint>

#define BB   64
#define SS   1024
#define II   256
#define HH   256
#define G3   768

typedef unsigned long long u64;

// Scratch for input-side gate projections: [B*S, 768] fp32
__device__ float g_xg[(size_t)BB * SS * G3];

__device__ __forceinline__ u64 ffma2(u64 a, u64 b, u64 c) {
    u64 d; asm("fma.rn.f32x2 %0, %1, %2, %3;" : "=l"(d) : "l"(a), "l"(b), "l"(c)); return d;
}
__device__ __forceinline__ float rcpa(float x) {
    float y; asm("rcp.approx.f32 %0, %1;" : "=f"(y) : "f"(x)); return y;
}
__device__ __forceinline__ float2 unpack2(u64 v) {
    float2 f; asm("mov.b64 {%0, %1}, %2;" : "=f"(f.x), "=f"(f.y) : "l"(v)); return f;
}
__device__ __forceinline__ u64 packdup(float x) {
    u64 v; asm("mov.b64 %0, {%1, %2};" : "=l"(v) : "f"(x), "f"(x)); return v;
}
__device__ __forceinline__ uint32_t smem_u32(const void* p) {
    return (uint32_t)__cvta_generic_to_shared(p);
}

// ---------------------------------------------------------------------------
// GEMM with f32x2 packed FMA (unchanged, passing).
// ---------------------------------------------------------------------------
__global__ void __launch_bounds__(256)
gemm_xg_kernel(const float* __restrict__ X, long lda,
               const float* __restrict__ W, const float* __restrict__ bias)
{
    __shared__ alignas(16) float As[16][132];
    __shared__ alignas(16) float Bs[16][68];

    const int t   = threadIdx.x;
    const int tx  = t & 15;
    const int ty  = t >> 4;
    const int r0  = blockIdx.y * 128;
    const int g0  = blockIdx.x * 64;

    const int arow = t >> 2;
    const int ak   = (t & 3) * 4;

    u64 acc2[4][4];
#pragma unroll
    for (int i = 0; i < 4; i++)
#pragma unroll
        for (int j = 0; j < 4; j++) acc2[i][j] = 0ull;

    for (int kt = 0; kt < 16; kt++) {
        const int k0 = kt * 16;
        float4 a0 = *reinterpret_cast<const float4*>(X + (size_t)(r0 + arow) * lda + k0 + ak);
        float4 a1 = *reinterpret_cast<const float4*>(X + (size_t)(r0 + arow + 64) * lda + k0 + ak);
        As[ak + 0][arow] = a0.x; As[ak + 1][arow] = a0.y;
        As[ak + 2][arow] = a0.z; As[ak + 3][arow] = a0.w;
        As[ak + 0][arow + 64] = a1.x; As[ak + 1][arow + 64] = a1.y;
        As[ak + 2][arow + 64] = a1.z; As[ak + 3][arow + 64] = a1.w;
        float4 bv = *reinterpret_cast<const float4*>(W + (size_t)(g0 + arow) * 256 + k0 + ak);
        Bs[ak + 0][arow] = bv.x; Bs[ak + 1][arow] = bv.y;
        Bs[ak + 2][arow] = bv.z; Bs[ak + 3][arow] = bv.w;
        __syncthreads();

#pragma unroll
        for (int kk = 0; kk < 16; kk++) {
            const u64* ap = reinterpret_cast<const u64*>(&As[kk][ty * 8]);
            u64 pa0 = ap[0], pa1 = ap[1], pa2 = ap[2], pa3 = ap[3];
            float4 bv4 = *reinterpret_cast<const float4*>(&Bs[kk][tx * 4]);
            u64 pb0 = packdup(bv4.x), pb1 = packdup(bv4.y);
            u64 pb2 = packdup(bv4.z), pb3 = packdup(bv4.w);
            acc2[0][0] = ffma2(pa0, pb0, acc2[0][0]);
            acc2[0][1] = ffma2(pa0, pb1, acc2[0][1]);
            acc2[0][2] = ffma2(pa0, pb2, acc2[0][2]);
            acc2[0][3] = ffma2(pa0, pb3, acc2[0][3]);
            acc2[1][0] = ffma2(pa1, pb0, acc2[1][0]);
            acc2[1][1] = ffma2(pa1, pb1, acc2[1][1]);
            acc2[1][2] = ffma2(pa1, pb2, acc2[1][2]);
            acc2[1][3] = ffma2(pa1, pb3, acc2[1][3]);
            acc2[2][0] = ffma2(pa2, pb0, acc2[2][0]);
            acc2[2][1] = ffma2(pa2, pb1, acc2[2][1]);
            acc2[2][2] = ffma2(pa2, pb2, acc2[2][2]);
            acc2[2][3] = ffma2(pa2, pb3, acc2[2][3]);
            acc2[3][0] = ffma2(pa3, pb0, acc2[3][0]);
            acc2[3][1] = ffma2(pa3, pb1, acc2[3][1]);
            acc2[3][2] = ffma2(pa3, pb2, acc2[3][2]);
            acc2[3][3] = ffma2(pa3, pb3, acc2[3][3]);
        }
        __syncthreads();
    }

    float4 b4 = *reinterpret_cast<const float4*>(bias + g0 + tx * 4);
#pragma unroll
    for (int i = 0; i < 4; i++) {
        float2 c0 = unpack2(acc2[i][0]), c1 = unpack2(acc2[i][1]);
        float2 c2 = unpack2(acc2[i][2]), c3 = unpack2(acc2[i][3]);
        size_t row0 = (size_t)(r0 + ty * 8 + 2 * i);
        float4 v0, v1;
        v0.x = c0.x + b4.x; v0.y = c1.x + b4.y; v0.z = c2.x + b4.z; v0.w = c3.x + b4.w;
        v1.x = c0.y + b4.x; v1.y = c1.y + b4.y; v1.z = c2.y + b4.z; v1.w = c3.y + b4.w;
        *reinterpret_cast<float4*>(&g_xg[row0 * G3 + g0 + tx * 4]) = v0;
        *reinterpret_cast<float4*>(&g_xg[(row0 + 1) * G3 + g0 + tx * 4]) = v1;
    }
}

// ---------------------------------------------------------------------------
// Persistent GRU scan. 4-CTA cluster per 2 batches, W_hh in registers.
//  - rbuf[parity][rank][sb][64]: contiguous per-rank slices, NO padding
//  - interleaved k-assignment (thread kc owns k = 32*i + 4*kc): conflict-free
//    128B-contiguous LDS.128 per 8-lane unit-group
//  - exchange = 3 x 512B cp.async.bulk smem->smem per step (minimal messages),
//    complete_tx on remote double-buffered mbarriers
// ---------------------------------------------------------------------------
__global__ void __cluster_dims__(4, 1, 1) __launch_bounds__(512, 1)
gru_scan_kernel(const float* __restrict__ Whh,   // [768,256]
                const float* __restrict__ bhh,   // [768]
                float* __restrict__ out, int ostride,
                float* __restrict__ out2, int ostride2)  // may be null
{
    __shared__ alignas(16) float rbuf[2][4][2][64];  // [parity][rank][sb][unit]
    __shared__ alignas(8)  u64   mbars[2];

    const int c    = blockIdx.x;               // cluster rank
    const int tid  = threadIdx.x;
    const int warp = tid >> 5;
    const int lane = tid & 31;
    const int ul   = warp * 4 + (lane >> 3);   // local unit 0..63
    const int jg   = c * 64 + ul;              // global hidden unit
    const int kc   = lane & 7;                 // k-slice id
    const bool leader = kc == 0;
    const int b0   = blockIdx.y * 2;

    // weights, interleaved-k order: pair j=2i   <-> k = 32i+4kc, 32i+4kc+1
    //                               pair j=2i+1 <-> k = 32i+4kc+2, +3
    u64 wr2[16], wz2[16], wn2[16];
#pragma unroll
    for (int i = 0; i < 8; i++) {
        const int k4 = 32 * i + 4 * kc;
        wr2[2*i]   = *reinterpret_cast<const u64*>(Whh + (size_t)jg * HH + k4);
        wr2[2*i+1] = *reinterpret_cast<const u64*>(Whh + (size_t)jg * HH + k4 + 2);
        wz2[2*i]   = *reinterpret_cast<const u64*>(Whh + (size_t)(256 + jg) * HH + k4);
        wz2[2*i+1] = *reinterpret_cast<const u64*>(Whh + (size_t)(256 + jg) * HH + k4 + 2);
        wn2[2*i]   = *reinterpret_cast<const u64*>(Whh + (size_t)(512 + jg) * HH + k4);
        wn2[2*i+1] = *reinterpret_cast<const u64*>(Whh + (size_t)(512 + jg) * HH + k4 + 2);
    }
    float bhr = 0.f, bhz = 0.f, bhn = 0.f;
    if (leader) { bhr = bhh[jg]; bhz = bhh[256 + jg]; bhn = bhh[512 + jg]; }

    // zero parity-0 buffer (512 floats == first 2048B)
    ((float*)rbuf)[tid] = 0.f;
    const uint32_t mb = smem_u32(mbars);
    const uint32_t hb = smem_u32(rbuf);
    if (tid == 0) {
        asm volatile("mbarrier.init.shared.b64 [%0], 1;" :: "r"(mb)     : "memory");
        asm volatile("mbarrier.init.shared.b64 [%0], 1;" :: "r"(mb + 8) : "memory");
    }
    __syncthreads();
    asm volatile("barrier.cluster.arrive.aligned;" ::: "memory");
    asm volatile("barrier.cluster.wait.aligned;"   ::: "memory");

    // hoisted per-rank remote bases
    uint32_t hb_r[4], mb_r[4];
#pragma unroll
    for (int r = 0; r < 4; r++) {
        asm volatile("mapa.shared::cluster.u32 %0, %1, %2;" : "=r"(hb_r[r]) : "r"(hb), "r"(r));
        asm volatile("mapa.shared::cluster.u32 %0, %1, %2;" : "=r"(mb_r[r]) : "r"(mb), "r"(r));
    }

    // prefetch xg for t=0 (leaders)
    float xpr[2], xpz[2], xpn[2];
    if (leader) {
#pragma unroll
        for (int sb = 0; sb < 2; sb++) {
            size_t base = ((size_t)(b0 + sb) * SS) * G3;
            xpr[sb] = __ldg(&g_xg[base + jg]);
            xpz[sb] = __ldg(&g_xg[base + 256 + jg]);
            xpn[sb] = __ldg(&g_xg[base + 512 + jg]);
        }
    }

    const int hrank = jg >> 6, hidx = jg & 63;
    int ph0 = 0, ph1 = 0;

    for (int t = 0; t < SS; t++) {
        const int p = t & 1, pq = p ^ 1;
        if (tid == 0) {
            // expect 3 remote 512B bulk copies into rbuf[pq]
            asm volatile("mbarrier.arrive.expect_tx.shared.b64 _, [%0], %1;"
                         :: "r"(mb + pq * 8), "r"(1536u) : "memory");
        }
        float xr[2], xz[2], xn[2];
        if (leader) {
#pragma unroll
            for (int sb = 0; sb < 2; sb++) { xr[sb]=xpr[sb]; xz[sb]=xpz[sb]; xn[sb]=xpn[sb]; }
            const int tn = (t + 1 < SS) ? t + 1 : t;
#pragma unroll
            for (int sb = 0; sb < 2; sb++) {
                size_t base = ((size_t)(b0 + sb) * SS + tn) * G3;
                xpr[sb] = __ldg(&g_xg[base + jg]);
                xpz[sb] = __ldg(&g_xg[base + 256 + jg]);
                xpn[sb] = __ldg(&g_xg[base + 512 + jg]);
            }
        }

#pragma unroll
        for (int sb = 0; sb < 2; sb++) {
            u64 aR = 0ull, aZ = 0ull, aN = 0ull;
#pragma unroll
            for (int i = 0; i < 8; i++) {
                const int k4 = 32 * i + 4 * kc;
                // h[k4..k4+3] lives at rbuf[p][k4>>6][sb][k4&63]; 8 lanes of a
                // unit-group read one contiguous 128B -> conflict-free LDS.128
                ulonglong2 hv = *reinterpret_cast<const ulonglong2*>(
                    &rbuf[p][k4 >> 6][sb][k4 & 63]);
                aR = ffma2(wr2[2*i],   hv.x, aR);
                aZ = ffma2(wz2[2*i],   hv.x, aZ);
                aN = ffma2(wn2[2*i],   hv.x, aN);
                aR = ffma2(wr2[2*i+1], hv.y, aR);
                aZ = ffma2(wz2[2*i+1], hv.y, aZ);
                aN = ffma2(wn2[2*i+1], hv.y, aN);
            }
            float2 fR = unpack2(aR), fZ = unpack2(aZ), fN = unpack2(aN);
            float sR = fR.x + fR.y, sZ = fZ.x + fZ.y, sN = fN.x + fN.y;
#pragma unroll
            for (int d = 4; d; d >>= 1) {
                sR += __shfl_down_sync(0xffffffffu, sR, d);
                sZ += __shfl_down_sync(0xffffffffu, sZ, d);
                sN += __shfl_down_sync(0xffffffffu, sN, d);
            }
            if (leader) {
                float er = __expf(-(xr[sb] + sR + bhr));
                float r  = rcpa(1.f + er);
                float ez = __expf(-(xz[sb] + sZ + bhz));
                float z  = rcpa(1.f + ez);
                float na = xn[sb] + r * (sN + bhn);
                float en = __expf(-2.f * na);
                float n  = (1.f - en) * rcpa(1.f + en);
                float hold = rbuf[p][hrank][sb][hidx];
                float hnew = n + z * (hold - n);

                size_t row = (size_t)(b0 + sb) * SS + t;
                out[row * ostride + jg] = hnew;
                if (out2) out2[row * ostride2 + jg] = hnew;

                rbuf[pq][c][sb][ul] = hnew;   // local write of own slice
            }
        }
        __syncthreads();

        // ship own 512B slice to the 3 other ranks as bulk DMA
        if (tid == 0) {
            asm volatile("fence.proxy.async.shared::cta;" ::: "memory");
            const uint32_t off = (uint32_t)(pq * 2048 + c * 512);
            const uint32_t src = hb + off;
#pragma unroll
            for (int r = 0; r < 4; r++) {
                if (r != c) {
                    asm volatile(
                        "cp.async.bulk.shared::cluster.shared::cta.mbarrier::complete_tx::bytes "
                        "[%0], [%1], %2, [%3];"
                        :: "r"(hb_r[r] + off), "r"(src), "r"(512u),
                           "r"(mb_r[r] + (uint32_t)(pq * 8)) : "memory");
                }
            }
        }

        // wait for the 3 remote slices of step t+1
        {
            uint32_t maddr = mb + pq * 8;
            uint32_t parity = pq ? ph1 : ph0;
            uint32_t done;
            asm volatile(
                "{\n\t.reg .pred p;\n\t"
                "mbarrier.try_wait.parity.acquire.cta.shared::cta.b64 p, [%1], %2;\n\t"
                "selp.b32 %0, 1, 0, p;\n\t}"
                : "=r"(done) : "r"(maddr), "r"(parity) : "memory");
            if (!done) {
                asm volatile(
                    "{\n\t.reg .pred P1;\n\t"
                    "WL_%=:\n\t"
                    "mbarrier.try_wait.parity.acquire.cta.shared::cta.b64 P1, [%0], %1, 0x989680;\n\t"
                    "@P1 bra.uni WD_%=;\n\t"
                    "bra.uni WL_%=;\n\t"
                    "WD_%=:\n\t}"
                    :: "r"(maddr), "r"(parity) : "memory");
            }
            if (pq) ph1 ^= 1; else ph0 ^= 1;
        }
    }
}

// ---------------------------------------------------------------------------
extern "C" void kernel_launch(void* const* d_in, const int* in_sizes, int n_in,
                              void* d_out, int out_size)
{
    (void)in_sizes; (void)n_in; (void)out_size;
    const float* inputs = (const float*)d_in[0];
    const float* W_ih0  = (const float*)d_in[1];
    const float* W_hh0  = (const float*)d_in[2];
    const float* b_ih0  = (const float*)d_in[3];
    const float* b_hh0  = (const float*)d_in[4];
    const float* W_ih1  = (const float*)d_in[5];
    const float* W_hh1  = (const float*)d_in[6];
    const float* b_ih1  = (const float*)d_in[7];
    const float* b_hh1  = (const float*)d_in[8];

    float* out    = (float*)d_out;
    float* h2     = out;                               // [B,S,H]
    float* concat = out + (size_t)BB * SS * HH;        // [B,S,2H]

    dim3 gemm_grid(G3 / 64, (BB * SS) / 128);
    dim3 scan_grid(4, BB / 2);

    // Layer 0
    gemm_xg_kernel<<<gemm_grid, 256>>>(inputs, (long)II, W_ih0, b_ih0);
    gru_scan_kernel<<<scan_grid, 512>>>(W_hh0, b_hh0, concat, 2 * HH, nullptr, 0);

    // Layer 1 (reads h1 from concat, lda = 512)
    gemm_xg_kernel<<<gemm_grid, 256>>>(concat, (long)(2 * HH), W_ih1, b_ih1);
    gru_scan_kernel<<<scan_grid, 512>>>(W_hh1, b_hh1, concat + HH, 2 * HH, h2, HH);
}